// round 17
// baseline (speedup 1.0000x reference)
#include <cuda_runtime.h>
#include <cuda_fp16.h>

// AttGCNEncoder: 2x GCNConv(relu) + single-token attention.
// softmax over length-1 axis == 1  =>  output = relu(gcn2) @ Wv + bv.
//
// R17 vs R16 (200.5us): GEMMs have only tile-local deps on the preceding
// aggregation -> fused:
//   k_fuse1 = aggr1 + gemm2 (128-node tiles, activations go SMEM-direct)
//   k_fuse2 = aggr2 + hi/lo-split Wv GEMM (64-node tiles)
// gemm2 output goes to g_b16 (not g_h16) to avoid racing concurrent readers.
// 6 launches. CSC build: count(returns slot)->scan->atomic-free fill.

#define FD 64
#define MAXN 100000
#define MAXE 3200000
#define MAXCOL (MAXE + 3 * MAXN + 16)

__device__ int    g_deg[MAXN];
__device__ int    g_rowstart[MAXN];
__device__ float  g_dis[MAXN];
__device__ __align__(16) int g_col[MAXCOL];
__device__ __align__(16) int g_eoff[MAXE + 4];      // per-edge slot within segment
__device__ __align__(16) __half g_h16[MAXN * FD];   // layer-1 dis-scaled linear out
__device__ __align__(16) __half g_b16[MAXN * FD];   // layer-2 dis-scaled linear out
__device__ unsigned long long g_bstate[1024];
__device__ int    g_is64;

typedef unsigned long long u64;
typedef unsigned int u32;

// ---------------- helpers ----------------
__device__ __forceinline__ u32 smem_u32(const void* p) {
    u32 a;
    asm("{ .reg .u64 t; cvta.to.shared.u64 t, %1; cvt.u32.u64 %0, t; }"
        : "=r"(a) : "l"(p));
    return a;
}
__device__ __forceinline__ u32 swz(u32 off) { return off ^ ((off >> 3) & 0x70); }
__device__ __forceinline__ u32 pack2(float a, float b) {
    __half2 h = __floats2half2_rn(a, b);
    return *reinterpret_cast<u32*>(&h);
}
__device__ __forceinline__ void ldmA(u32& a0, u32& a1, u32& a2, u32& a3, u32 addr) {
    asm volatile("ldmatrix.sync.aligned.m8n8.x4.shared.b16 {%0,%1,%2,%3}, [%4];"
                 : "=r"(a0), "=r"(a1), "=r"(a2), "=r"(a3) : "r"(addr));
}
__device__ __forceinline__ void ldmB(u32& b0, u32& b1, u32 addr) {
    asm volatile("ldmatrix.sync.aligned.m8n8.x2.trans.shared.b16 {%0,%1}, [%2];"
                 : "=r"(b0), "=r"(b1) : "r"(addr));
}
__device__ __forceinline__ void mma16816(float* c, u32 a0, u32 a1, u32 a2, u32 a3,
                                         u32 b0, u32 b1) {
    asm volatile(
        "mma.sync.aligned.m16n8k16.row.col.f32.f16.f16.f32 "
        "{%0,%1,%2,%3}, {%4,%5,%6,%7}, {%8,%9}, {%0,%1,%2,%3};"
        : "+f"(c[0]), "+f"(c[1]), "+f"(c[2]), "+f"(c[3])
        : "r"(a0), "r"(a1), "r"(a2), "r"(a3), "r"(b0), "r"(b1));
}

// ---------------------------------------------------------------------------
// zero deg + lookback state + dtype sniff
// ---------------------------------------------------------------------------
__global__ void k_zero_sniff(const int* __restrict__ ei32, int n) {
    int i = blockIdx.x * blockDim.x + threadIdx.x;
    if (i < n) g_deg[i] = 0;
    if (i < 1024) g_bstate[i] = 0ull;
    if (i == 0) {
        int acc = 0;
#pragma unroll
        for (int j = 0; j < 16; j++) acc |= ei32[2 * j + 1];
        g_is64 = (acc == 0) ? 1 : 0;
    }
}

// ---------------------------------------------------------------------------
// k_count: 4 edges/thread; atomicAdd return = within-segment slot -> g_eoff
// ---------------------------------------------------------------------------
__global__ void k_count(const void* __restrict__ ei, int e, int n, int vec_ok) {
    int b = (blockIdx.x * blockDim.x + threadIdx.x) * 4;
    if (b >= e) return;
    int d[4];
    if (g_is64) {
        const long long* dst = (const long long*)ei + e;
        if (vec_ok && b + 3 < e) {
            longlong2 p0 = __ldg((const longlong2*)(dst + b));
            longlong2 p1 = __ldg((const longlong2*)(dst + b + 2));
            d[0] = (int)p0.x; d[1] = (int)p0.y; d[2] = (int)p1.x; d[3] = (int)p1.y;
        } else {
#pragma unroll
            for (int k = 0; k < 4; k++) d[k] = (b + k < e) ? (int)dst[b + k] : -1;
        }
    } else {
        const int* dst = (const int*)ei + e;
        if (vec_ok && b + 3 < e) {
            int4 p = __ldg((const int4*)(dst + b));
            d[0] = p.x; d[1] = p.y; d[2] = p.z; d[3] = p.w;
        } else {
#pragma unroll
            for (int k = 0; k < 4; k++) d[k] = (b + k < e) ? dst[b + k] : -1;
        }
    }
    int off[4];
#pragma unroll
    for (int k = 0; k < 4; k++) {
        off[k] = 0;
        if (b + k < e && d[k] >= 0 && d[k] < n)
            off[k] = atomicAdd(&g_deg[d[k]], 1);
    }
    if (vec_ok && b + 3 < e) {
        *(int4*)(g_eoff + b) = make_int4(off[0], off[1], off[2], off[3]);
    } else {
#pragma unroll
        for (int k = 0; k < 4; k++)
            if (b + k < e) g_eoff[b + k] = off[k];
    }
}

// ---------------------------------------------------------------------------
// Single-pass decoupled-lookback scan (proven)
// ---------------------------------------------------------------------------
__global__ void k_scan(int n) {
    __shared__ int s[256];
    __shared__ int s_excl;
    int t = threadIdx.x;
    int i = blockIdx.x * 256 + t;
    int deg = (i < n) ? g_deg[i] : 0;
    int v = (deg + 3) & ~3;
    s[t] = v;
    __syncthreads();
#pragma unroll
    for (int off = 1; off < 256; off <<= 1) {
        int x = (t >= off) ? s[t - off] : 0;
        __syncthreads();
        s[t] += x;
        __syncthreads();
    }
    int blocksum = s[255];
    if (t == 0) {
        int excl = 0;
        if (blockIdx.x > 0) {
            atomicExch(&g_bstate[blockIdx.x], (1ull << 32) | (unsigned)blocksum);
            for (int b = blockIdx.x - 1;;) {
                unsigned long long st;
                do { st = atomicAdd(&g_bstate[b], 0ull); } while ((st >> 32) == 0);
                excl += (int)(unsigned)st;
                if ((st >> 32) == 2) break;
                b--;
            }
        }
        atomicExch(&g_bstate[blockIdx.x], (2ull << 32) | (unsigned)(excl + blocksum));
        s_excl = excl;
    }
    __syncthreads();
    if (i < n) {
        g_rowstart[i] = s_excl + s[t] - v;
        g_dis[i] = rsqrtf((float)(deg + 1));
    }
}

// ---------------------------------------------------------------------------
// fill body: atomic-free. p = rowstart[dst] + eoff[i]; g_col[p] = src.
// ---------------------------------------------------------------------------
__device__ __forceinline__ void fill_body(const void* __restrict__ ei, int e,
                                          int n, int vec_ok, int bid, int tid) {
    int b = (bid * 256 + tid) * 4;
    if (b >= e) return;
    int sI[4], dI[4], oI[4];
    if (g_is64) {
        const long long* src = (const long long*)ei;
        const long long* dst = src + e;
        if (vec_ok && b + 3 < e) {
            longlong2 s0 = __ldg((const longlong2*)(src + b));
            longlong2 s1 = __ldg((const longlong2*)(src + b + 2));
            longlong2 d0 = __ldg((const longlong2*)(dst + b));
            longlong2 d1 = __ldg((const longlong2*)(dst + b + 2));
            sI[0]=(int)s0.x; sI[1]=(int)s0.y; sI[2]=(int)s1.x; sI[3]=(int)s1.y;
            dI[0]=(int)d0.x; dI[1]=(int)d0.y; dI[2]=(int)d1.x; dI[3]=(int)d1.y;
        } else {
#pragma unroll
            for (int k = 0; k < 4; k++) {
                sI[k] = (b + k < e) ? (int)src[b + k] : -1;
                dI[k] = (b + k < e) ? (int)dst[b + k] : -1;
            }
        }
    } else {
        const int* src = (const int*)ei;
        const int* dst = src + e;
        if (vec_ok && b + 3 < e) {
            int4 sp = __ldg((const int4*)(src + b));
            int4 dp = __ldg((const int4*)(dst + b));
            sI[0]=sp.x; sI[1]=sp.y; sI[2]=sp.z; sI[3]=sp.w;
            dI[0]=dp.x; dI[1]=dp.y; dI[2]=dp.z; dI[3]=dp.w;
        } else {
#pragma unroll
            for (int k = 0; k < 4; k++) {
                sI[k] = (b + k < e) ? src[b + k] : -1;
                dI[k] = (b + k < e) ? dst[b + k] : -1;
            }
        }
    }
    if (vec_ok && b + 3 < e) {
        int4 op = *(const int4*)(g_eoff + b);
        oI[0] = op.x; oI[1] = op.y; oI[2] = op.z; oI[3] = op.w;
    } else {
#pragma unroll
        for (int k = 0; k < 4; k++) oI[k] = (b + k < e) ? g_eoff[b + k] : 0;
    }
#pragma unroll
    for (int k = 0; k < 4; k++) {
        if (b + k < e && sI[k] >= 0 && sI[k] < n && dI[k] >= 0 && dI[k] < n) {
            int p = __ldg(&g_rowstart[dI[k]]) + oI[k];
            g_col[p] = sI[k];
        }
    }
}

// ---------------------------------------------------------------------------
// aggregation gather (pre-bias/relu sum) for one node; warp-collective,
// lane owns cols 2*lane, 2*lane+1.
// ---------------------------------------------------------------------------
__device__ __forceinline__ float2 aggr_gather(const __half* __restrict__ hbuf,
                                              int i, int lane) {
    const __half2* h2 = (const __half2*)hbuf;
    float2 self = __half22float2(__ldg(&h2[i * 32 + lane]));
    float ax = self.x, ay = self.y;

    int start = __ldg(&g_rowstart[i]);
    int len   = __ldg(&g_deg[i]);
    const int4* c4 = (const int4*)(g_col + start);
    int nf = len >> 2;
#pragma unroll 2
    for (int q = 0; q < nf; q++) {
        int4 cc = __ldg(&c4[q]);
        float2 v0 = __half22float2(__ldg(&h2[cc.x * 32 + lane]));
        float2 v1 = __half22float2(__ldg(&h2[cc.y * 32 + lane]));
        float2 v2 = __half22float2(__ldg(&h2[cc.z * 32 + lane]));
        float2 v3 = __half22float2(__ldg(&h2[cc.w * 32 + lane]));
        ax += (v0.x + v1.x) + (v2.x + v3.x);
        ay += (v0.y + v1.y) + (v2.y + v3.y);
    }
    for (int j = nf * 4; j < len; j++) {
        int s = __ldg(&g_col[start + j]);
        float2 v = __half22float2(__ldg(&h2[s * 32 + lane]));
        ax += v.x;
        ay += v.y;
    }
    return make_float2(ax, ay);
}

// ---------------------------------------------------------------------------
// HMMA gemm body for gemm1 (fp32 x input): 128 rows/tile -> g_h16 (dis-scaled)
// ---------------------------------------------------------------------------
__device__ __forceinline__ void hgemm_body(const float* __restrict__ Af32,
                                           const float* __restrict__ W,
                                           int n, int rowbase,
                                           __half* sA, __half* sB, int tid) {
    char* sAb = (char*)sA;
    char* sBb = (char*)sB;

#pragma unroll
    for (int it = 0; it < 4; it++) {
        int idx = tid + it * 256;
        int r = idx >> 3, c = idx & 7;
        int gr = rowbase + r;
        uint4 v;
        if (gr < n) {
            const float4* s = (const float4*)(Af32 + (size_t)gr * FD + c * 8);
            float4 f0 = __ldg(s), f1 = __ldg(s + 1);
            v.x = pack2(f0.x, f0.y); v.y = pack2(f0.z, f0.w);
            v.z = pack2(f1.x, f1.y); v.w = pack2(f1.z, f1.w);
        } else v = make_uint4(0, 0, 0, 0);
        *(uint4*)(sAb + swz((u32)(r * 128 + c * 16))) = v;
    }
#pragma unroll
    for (int it = 0; it < 2; it++) {
        int idx = tid + it * 256;
        int k = idx >> 3, c = idx & 7;
        const float4* s = (const float4*)(W + (size_t)k * FD + c * 8);
        float4 f0 = __ldg(s), f1 = __ldg(s + 1);
        uint4 v;
        v.x = pack2(f0.x, f0.y); v.y = pack2(f0.z, f0.w);
        v.z = pack2(f1.x, f1.y); v.w = pack2(f1.z, f1.w);
        *(uint4*)(sBb + swz((u32)(k * 128 + c * 16))) = v;
    }
    __syncthreads();

    int lane = tid & 31;
    int warp = tid >> 5;
    u32 baseA = smem_u32(sA);
    u32 baseB = smem_u32(sB);

    u32 a[4][4];
    {
        int r = warp * 16 + (lane & 15);
        int cbyte = (lane >> 4) * 16;
#pragma unroll
        for (int k = 0; k < 4; k++)
            ldmA(a[k][0], a[k][1], a[k][2], a[k][3],
                 baseA + swz((u32)(r * 128 + cbyte + k * 32)));
    }

    float c[8][4];
#pragma unroll
    for (int nt = 0; nt < 8; nt++)
#pragma unroll
        for (int j = 0; j < 4; j++) c[nt][j] = 0.f;

#pragma unroll
    for (int k = 0; k < 4; k++) {
        int br = k * 16 + (lane & 15);
#pragma unroll
        for (int nt = 0; nt < 8; nt++) {
            u32 b0, b1;
            ldmB(b0, b1, baseB + swz((u32)(br * 128 + nt * 16)));
            mma16816(c[nt], a[k][0], a[k][1], a[k][2], a[k][3], b0, b1);
        }
    }

    int gr0 = rowbase + warp * 16 + (lane >> 2);
    int gr1 = gr0 + 8;
    float d0 = (gr0 < n) ? g_dis[gr0] : 0.f;
    float d1 = (gr1 < n) ? g_dis[gr1] : 0.f;
#pragma unroll
    for (int nt = 0; nt < 8; nt++) {
        int col = nt * 8 + (lane & 3) * 2;
        if (gr0 < n)
            *(__half2*)(g_h16 + (size_t)gr0 * FD + col) =
                __floats2half2_rn(d0 * c[nt][0], d0 * c[nt][1]);
        if (gr1 < n)
            *(__half2*)(g_h16 + (size_t)gr1 * FD + col) =
                __floats2half2_rn(d1 * c[nt][2], d1 * c[nt][3]);
    }
}

// ---------------------------------------------------------------------------
// Merged: blocks [0,gb) run gemm1 (x@W1 -> g_h16); rest run atomic-free fill.
// ---------------------------------------------------------------------------
__global__ __launch_bounds__(256) void k_gemm1_fill(const float* __restrict__ x,
                                                    const float* __restrict__ W1,
                                                    const void* __restrict__ ei,
                                                    int e, int n, int vec_ok,
                                                    int gb) {
    __shared__ __align__(1024) __half sA[128 * FD];
    __shared__ __align__(1024) __half sB[FD * FD];
    if ((int)blockIdx.x < gb) {
        hgemm_body(x, W1, n, blockIdx.x * 128, sA, sB, threadIdx.x);
    } else {
        fill_body(ei, e, n, vec_ok, blockIdx.x - gb, threadIdx.x);
    }
}

// ---------------------------------------------------------------------------
// k_fuse1: aggr1 + gemm2 fused. 128 nodes/block, 256 threads.
// Phase 1: each warp aggregates 16 nodes from g_h16, applies b1+relu,
//          stores fp16 activation rows straight into swizzled SMEM A-tile.
// Phase 2: HMMA vs W2, epilogue dis-scale -> g_b16.
// ---------------------------------------------------------------------------
__global__ __launch_bounds__(256) void k_fuse1(const float* __restrict__ b1,
                                               const float* __restrict__ W2,
                                               int n) {
    __shared__ __align__(1024) __half sA[128 * FD];
    __shared__ __align__(1024) __half sB[FD * FD];

    int tid = threadIdx.x;
    int lane = tid & 31;
    int warp = tid >> 5;
    int base = blockIdx.x * 128;
    char* sAb = (char*)sA;
    char* sBb = (char*)sB;

    // Stage B = fp16(W2) (independent of aggregation; issue loads early)
#pragma unroll
    for (int it = 0; it < 2; it++) {
        int idx = tid + it * 256;
        int k = idx >> 3, c = idx & 7;
        const float4* s = (const float4*)(W2 + (size_t)k * FD + c * 8);
        float4 f0 = __ldg(s), f1 = __ldg(s + 1);
        uint4 v;
        v.x = pack2(f0.x, f0.y); v.y = pack2(f0.z, f0.w);
        v.z = pack2(f1.x, f1.y); v.w = pack2(f1.z, f1.w);
        *(uint4*)(sBb + swz((u32)(k * 128 + c * 16))) = v;
    }

    // Phase 1: aggregate 16 nodes per warp -> SMEM A-tile
    float bx = __ldg(&b1[2 * lane]), by = __ldg(&b1[2 * lane + 1]);
    for (int t = 0; t < 16; t++) {
        int r = warp * 16 + t;
        int i = base + r;
        float vx = 0.f, vy = 0.f;
        if (i < n) {
            float2 s = aggr_gather(g_h16, i, lane);
            float di = g_dis[i];
            vx = fmaxf(fmaf(di, s.x, bx), 0.f);
            vy = fmaxf(fmaf(di, s.y, by), 0.f);
        }
        *(__half2*)(sAb + swz((u32)(r * 128 + lane * 4))) =
            __floats2half2_rn(vx, vy);
    }
    __syncthreads();

    // Phase 2: HMMA
    u32 baseA = smem_u32(sA);
    u32 baseB = smem_u32(sB);

    u32 a[4][4];
    {
        int r = warp * 16 + (lane & 15);
        int cbyte = (lane >> 4) * 16;
#pragma unroll
        for (int k = 0; k < 4; k++)
            ldmA(a[k][0], a[k][1], a[k][2], a[k][3],
                 baseA + swz((u32)(r * 128 + cbyte + k * 32)));
    }

    float c[8][4];
#pragma unroll
    for (int nt = 0; nt < 8; nt++)
#pragma unroll
        for (int j = 0; j < 4; j++) c[nt][j] = 0.f;

#pragma unroll
    for (int k = 0; k < 4; k++) {
        int br = k * 16 + (lane & 15);
#pragma unroll
        for (int nt = 0; nt < 8; nt++) {
            u32 b0, b1r;
            ldmB(b0, b1r, baseB + swz((u32)(br * 128 + nt * 16)));
            mma16816(c[nt], a[k][0], a[k][1], a[k][2], a[k][3], b0, b1r);
        }
    }

    int gr0 = base + warp * 16 + (lane >> 2);
    int gr1 = gr0 + 8;
    float d0 = (gr0 < n) ? g_dis[gr0] : 0.f;
    float d1 = (gr1 < n) ? g_dis[gr1] : 0.f;
#pragma unroll
    for (int nt = 0; nt < 8; nt++) {
        int col = nt * 8 + (lane & 3) * 2;
        if (gr0 < n)
            *(__half2*)(g_b16 + (size_t)gr0 * FD + col) =
                __floats2half2_rn(d0 * c[nt][0], d0 * c[nt][1]);
        if (gr1 < n)
            *(__half2*)(g_b16 + (size_t)gr1 * FD + col) =
                __floats2half2_rn(d1 * c[nt][2], d1 * c[nt][3]);
    }
}

// ---------------------------------------------------------------------------
// k_fuse2: aggr2 + hi/lo-split Wv GEMM. 64 nodes/block, 128 threads.
// Phase 1: each of 4 warps aggregates 16 nodes from g_b16, applies b2+relu
//          (fp32), splits hi/lo fp16, stores into swizzled SMEM tiles.
// Phase 2: 3-pass HMMA (AhWh + AlWh + AhWl) + bv -> outf (fp32).
// ---------------------------------------------------------------------------
__global__ __launch_bounds__(128) void k_fuse2(const float* __restrict__ b2,
                                               const float* __restrict__ Wv,
                                               const float* __restrict__ bias,
                                               float* __restrict__ outf, int n) {
    __shared__ __align__(1024) __half sAh[64 * FD];
    __shared__ __align__(1024) __half sAl[64 * FD];
    __shared__ __align__(1024) __half sBh[FD * FD];
    __shared__ __align__(1024) __half sBl[FD * FD];

    int tid = threadIdx.x;
    int lane = tid & 31;
    int warp = tid >> 5;
    int base = blockIdx.x * 64;
    char *sAhb = (char*)sAh, *sAlb = (char*)sAl;
    char *sBhb = (char*)sBh, *sBlb = (char*)sBl;

    // Stage Wv hi/lo
#pragma unroll
    for (int it = 0; it < 4; it++) {
        int idx = tid + it * 128;
        int k = idx >> 3, c = idx & 7;
        const float4* s = (const float4*)(Wv + (size_t)k * FD + c * 8);
        float4 f0 = __ldg(s), f1 = __ldg(s + 1);
        float f[8] = {f0.x,f0.y,f0.z,f0.w,f1.x,f1.y,f1.z,f1.w};
        u32 ph[4], pl[4];
#pragma unroll
        for (int q = 0; q < 4; q++) {
            __half h0 = __float2half_rn(f[2*q]);
            __half h1 = __float2half_rn(f[2*q+1]);
            __half l0 = __float2half_rn(f[2*q]   - __half2float(h0));
            __half l1 = __float2half_rn(f[2*q+1] - __half2float(h1));
            __half2 hh = __halves2half2(h0, h1);
            __half2 ll = __halves2half2(l0, l1);
            ph[q] = *reinterpret_cast<u32*>(&hh);
            pl[q] = *reinterpret_cast<u32*>(&ll);
        }
        u32 off = swz((u32)(k * 128 + c * 16));
        *(uint4*)(sBhb + off) = make_uint4(ph[0], ph[1], ph[2], ph[3]);
        *(uint4*)(sBlb + off) = make_uint4(pl[0], pl[1], pl[2], pl[3]);
    }

    // Phase 1: aggregate 16 nodes per warp, split hi/lo -> SMEM
    float bx = __ldg(&b2[2 * lane]), by = __ldg(&b2[2 * lane + 1]);
    for (int t = 0; t < 16; t++) {
        int r = warp * 16 + t;
        int i = base + r;
        float vx = 0.f, vy = 0.f;
        if (i < n) {
            float2 s = aggr_gather(g_b16, i, lane);
            float di = g_dis[i];
            vx = fmaxf(fmaf(di, s.x, bx), 0.f);
            vy = fmaxf(fmaf(di, s.y, by), 0.f);
        }
        __half hx = __float2half_rn(vx), hy = __float2half_rn(vy);
        __half lx = __float2half_rn(vx - __half2float(hx));
        __half ly = __float2half_rn(vy - __half2float(hy));
        u32 off = swz((u32)(r * 128 + lane * 4));
        *(__half2*)(sAhb + off) = __halves2half2(hx, hy);
        *(__half2*)(sAlb + off) = __halves2half2(lx, ly);
    }
    __syncthreads();

    // Phase 2: 3-pass split HMMA
    u32 bAh = smem_u32(sAh), bAl = smem_u32(sAl);
    u32 bBh = smem_u32(sBh), bBl = smem_u32(sBl);

    u32 ah[4][4], al[4][4];
    {
        int r = warp * 16 + (lane & 15);
        int cbyte = (lane >> 4) * 16;
#pragma unroll
        for (int k = 0; k < 4; k++) {
            u32 off = swz((u32)(r * 128 + cbyte + k * 32));
            ldmA(ah[k][0], ah[k][1], ah[k][2], ah[k][3], bAh + off);
            ldmA(al[k][0], al[k][1], al[k][2], al[k][3], bAl + off);
        }
    }

    float c[8][4];
#pragma unroll
    for (int nt = 0; nt < 8; nt++)
#pragma unroll
        for (int j = 0; j < 4; j++) c[nt][j] = 0.f;

#pragma unroll
    for (int k = 0; k < 4; k++) {
        int br = k * 16 + (lane & 15);
#pragma unroll
        for (int nt = 0; nt < 8; nt++) {
            u32 off = swz((u32)(br * 128 + nt * 16));
            u32 bh0, bh1, bl0, bl1;
            ldmB(bh0, bh1, bBh + off);
            ldmB(bl0, bl1, bBl + off);
            mma16816(c[nt], ah[k][0], ah[k][1], ah[k][2], ah[k][3], bh0, bh1);
            mma16816(c[nt], al[k][0], al[k][1], al[k][2], al[k][3], bh0, bh1);
            mma16816(c[nt], ah[k][0], ah[k][1], ah[k][2], ah[k][3], bl0, bl1);
        }
    }

    int gr0 = base + warp * 16 + (lane >> 2);
    int gr1 = gr0 + 8;
#pragma unroll
    for (int nt = 0; nt < 8; nt++) {
        int col = nt * 8 + (lane & 3) * 2;
        float vbx = __ldg(&bias[col]), vby = __ldg(&bias[col + 1]);
        if (gr0 < n)
            *(float2*)(outf + (size_t)gr0 * FD + col) =
                make_float2(c[nt][0] + vbx, c[nt][1] + vby);
        if (gr1 < n)
            *(float2*)(outf + (size_t)gr1 * FD + col) =
                make_float2(c[nt][2] + vbx, c[nt][3] + vby);
    }
}

// ---------------------------------------------------------------------------
// Launch — kernel launches ONLY (graph-capture-safe)
// ---------------------------------------------------------------------------
extern "C" void kernel_launch(void* const* d_in, const int* in_sizes, int n_in,
                              void* d_out, int out_size) {
    const float* x  = (const float*)d_in[0];
    const void*  ei = d_in[1];
    const float* W1 = (const float*)d_in[2];
    const float* b1 = (const float*)d_in[3];
    const float* W2 = (const float*)d_in[4];
    const float* b2 = (const float*)d_in[5];
    // d_in[6..9] = Wq,bq,Wk,bk : dead (softmax over length-1 axis == 1)
    const float* Wv = (const float*)d_in[10];
    const float* bv = (const float*)d_in[11];

    int n = in_sizes[0] / FD;
    int e = in_sizes[1] / 2;
    float* outp = (float*)d_out;

    int vec_ok = ((e & 3) == 0) ? 1 : 0;
    int nb  = (n + 255) / 256;
    int e4  = (e + 1023) / 1024;
    int hg_blocks = (n + 127) / 128;
    int f1_blocks = (n + 127) / 128;
    int f2_blocks = (n + 63) / 64;

    k_zero_sniff<<<nb, 256>>>((const int*)ei, n);                      // 0
    k_count<<<e4, 256>>>(ei, e, n, vec_ok);                            // 1
    k_scan<<<nb, 256>>>(n);                                            // 2
    k_gemm1_fill<<<hg_blocks + e4, 256>>>(x, W1, ei, e, n, vec_ok,
                                          hg_blocks);                  // 3
    k_fuse1<<<f1_blocks, 256>>>(b1, W2, n);                            // 4
    k_fuse2<<<f2_blocks, 128>>>(b2, Wv, bv, outp, n);                  // 5
}